// round 2
// baseline (speedup 1.0000x reference)
#include <cuda_runtime.h>

typedef unsigned long long u64;

// ---------------- packed f32x2 primitives (sm_103a) ----------------
static __device__ __forceinline__ u64 pk(float lo, float hi) {
    u64 r; asm("mov.b64 %0, {%1, %2};" : "=l"(r) : "f"(lo), "f"(hi)); return r;
}
static __device__ __forceinline__ void upk(u64 v, float& lo, float& hi) {
    asm("mov.b64 {%0, %1}, %2;" : "=f"(lo), "=f"(hi) : "l"(v));
}
static __device__ __forceinline__ u64 ffma2(u64 a, u64 b, u64 c) {
    u64 d; asm("fma.rn.f32x2 %0, %1, %2, %3;" : "=l"(d) : "l"(a), "l"(b), "l"(c)); return d;
}
static __device__ __forceinline__ u64 mul2(u64 a, u64 b) {
    u64 d; asm("mul.rn.f32x2 %0, %1, %2;" : "=l"(d) : "l"(a), "l"(b)); return d;
}
static __device__ __forceinline__ u64 add2(u64 a, u64 b) {
    u64 d; asm("add.rn.f32x2 %0, %1, %2;" : "=l"(d) : "l"(a), "l"(b)); return d;
}

// packed-pair float constants (both lanes identical; bit patterns hand-encoded)
static constexpr u64 C_2LOG2E = 0x4038AA3B4038AA3Bull; // 2*log2(e) = 2.8853900f
static constexpr u64 C_ONE    = 0x3F8000003F800000ull; // 1.0f
static constexpr u64 C_NEG2   = 0xC0000000C0000000ull; // -2.0f

// accurate tanh on a packed pair: 1 - 2/(e^{2x}+1), fma-side done packed.
static __device__ __forceinline__ u64 tanh2(u64 v) {
    u64 s = mul2(v, C_2LOG2E);
    float a, b; upk(s, a, b);
    float ea, eb;
    asm("ex2.approx.f32 %0, %1;" : "=f"(ea) : "f"(a));
    asm("ex2.approx.f32 %0, %1;" : "=f"(eb) : "f"(b));
    u64 ep = add2(pk(ea, eb), C_ONE);
    float p, q; upk(ep, p, q);
    float rp_, rq_;
    asm("rcp.approx.f32 %0, %1;" : "=f"(rp_) : "f"(p));
    asm("rcp.approx.f32 %0, %1;" : "=f"(rq_) : "f"(q));
    return ffma2(C_NEG2, pk(rp_, rq_), C_ONE);
}

// ---------------- shared-memory weight layout (u64 = {w,w} dup pairs) ----------------
// All segment offsets are EVEN (16B-aligned) and all row strides are even so
// that weight pairs can be fetched with LDS.128 (ulonglong2).
static constexpr int OW1  = 0;              // [2][30]
static constexpr int OB1  = OW1  + 60;      // [30]
static constexpr int OW2  = OB1  + 30;      // [30][30]
static constexpr int OB2  = OW2  + 900;     // [30]
static constexpr int OW3  = OB2  + 30;      // [30][30]
static constexpr int OB3  = OW3  + 900;     // [30]
static constexpr int OW4  = OB3  + 30;      // [30][8]
static constexpr int OB4  = OW4  + 240;     // [8]
static constexpr int OP1  = OB4  + 8;       // [2][16]  (15 real cols, col 15 = 0)
static constexpr int OPB1 = OP1  + 32;      // [16]
static constexpr int OP2  = OPB1 + 16;      // [15][16]
static constexpr int OPB2 = OP2  + 240;     // [16]
static constexpr int OP3  = OPB2 + 16;      // [15][16]
static constexpr int OPB3 = OP3  + 240;     // [16]
static constexpr int OP4  = OPB3 + 16;      // [15][4]
static constexpr int OPB4 = OP4  + 60;      // [4]
static constexpr int SMW_TOTAL = OPB4 + 4;  // 2822 u64 = 22576 B

// ---------------- dense layer with paired (LDS.128) weight loads ----------------
// NO must be even; W rows are stride-NO and 16B-aligned.
template <int NI, int NO>
static __device__ __forceinline__ void dense2(const u64* __restrict__ W,
                                              const u64* __restrict__ Bias,
                                              const u64* __restrict__ in,
                                              u64* __restrict__ out) {
#pragma unroll
    for (int j = 0; j < NO; j += 2) {
        ulonglong2 b2 = *(const ulonglong2*)(Bias + j);
        out[j] = b2.x; out[j + 1] = b2.y;
    }
#pragma unroll
    for (int k = 0; k < NI; k++) {
        u64 hk = in[k];
#pragma unroll
        for (int j = 0; j < NO; j += 2) {
            ulonglong2 w2 = *(const ulonglong2*)(W + k * NO + j);
            out[j]     = ffma2(w2.x, hk, out[j]);
            out[j + 1] = ffma2(w2.y, hk, out[j + 1]);
        }
    }
}
template <int NN>
static __device__ __forceinline__ void tanh_all(u64* v) {
#pragma unroll
    for (int j = 0; j < NN; j++) v[j] = tanh2(v[j]);
}

// ---------------- half-angle: sin(θ/2), cos(θ/2) from cosθ, sinθ ----------------
static __device__ __forceinline__ void halfang(float c, float sn, float& sh, float& ch) {
    ch = sqrtf(fmaxf(0.0f, 0.5f * (1.0f + c)));
    float sh_a = copysignf(sqrtf(fmaxf(0.0f, 0.5f * (1.0f - c))), sn);
    float sh_b = __fdividef(0.5f * sn, ch);
    sh = (ch > 0.1f) ? sh_b : sh_a;
}

// ---------------- per-point epilogue ----------------
static __device__ __forceinline__ float epilogue(
    float x0, float x1, float r, float cb, float sb,
    const float* wv, const float* pv, float lm)
{
    float s2  = fmaf(x0, x0, x1 * x1);
    float ri0 = rsqrtf(s2);
    float r0  = s2 * ri0;
    float c   = x0 * ri0, sn = x1 * ri0;
    float sh, ch; halfang(c, sn, sh, ch);
    float sq  = sqrtf(r0);
    float v0  = sq * sh;
    float v1  = r0 * sn;
    float v2  = (r0 * sq) * fmaf(sn, ch, c * sh);
    float shb, chb; halfang(cb, sb, shb, chb);
    float u0 = shb, u1 = sb, u2 = fmaf(sb, chb, cb * shb);
    float t  = fminf(fmaxf(fmaf(2.5f, r, -1.25f), 0.0f), 1.0f);
    float t3 = t * t * t;
    float yita = fmaf(fmaf(fmaf(-6.0f, t, 15.0f), t, -10.0f), t3, 1.0f);
    float rp = wv[0] + yita * wv[4]
             + fmaf(wv[5], yita, wv[1]) * v0
             + fmaf(wv[6], yita, wv[2]) * v1
             + fmaf(wv[7], yita, wv[3]) * v2;
    float s  = fmaf(pv[1], u0, fmaf(pv[2], u1, fmaf(pv[3], u2, pv[0])));
    float sp = s * yita * __powf(r, lm);
    return rp + sp;
}

// ---------------- kernel: 2 points per thread, packed into f32x2 lanes ----------------
__global__ void __launch_bounds__(128, 3)
mlp2d_kernel(const float* __restrict__ x,   const float* __restrict__ imv,
             const float* __restrict__ lmbd,
             const float* __restrict__ Ww1, const float* __restrict__ bw1,
             const float* __restrict__ Ww2, const float* __restrict__ bw2,
             const float* __restrict__ Ww3, const float* __restrict__ bw3,
             const float* __restrict__ Ww4, const float* __restrict__ bw4,
             const float* __restrict__ Wp1, const float* __restrict__ bp1,
             const float* __restrict__ Wp2, const float* __restrict__ bp2,
             const float* __restrict__ Wp3, const float* __restrict__ bp3,
             const float* __restrict__ Wp4, const float* __restrict__ bp4,
             float* __restrict__ out, int N)
{
    __shared__ alignas(16) u64 smw[SMW_TOTAL];
    __shared__ float scons[3];

    const int tid = threadIdx.x;
    // cooperative duplicated-pair weight load with column/row padding (zeros)
    {
        struct Seg { int off; int rows; int cols; int pad; };
        const Seg segs[16] = {
            {OW1, 2, 30, 30}, {OB1, 1, 30, 30},
            {OW2, 30, 30, 30}, {OB2, 1, 30, 30},
            {OW3, 30, 30, 30}, {OB3, 1, 30, 30},
            {OW4, 30, 8, 8},   {OB4, 1, 8, 8},
            {OP1, 2, 15, 16},  {OPB1, 1, 15, 16},
            {OP2, 15, 15, 16}, {OPB2, 1, 15, 16},
            {OP3, 15, 15, 16}, {OPB3, 1, 15, 16},
            {OP4, 15, 4, 4},   {OPB4, 1, 4, 4},
        };
        const float* srcs[16] = {Ww1, bw1, Ww2, bw2, Ww3, bw3, Ww4, bw4,
                                 Wp1, bp1, Wp2, bp2, Wp3, bp3, Wp4, bp4};
        for (int a = 0; a < 16; a++) {
            const Seg s = segs[a];
            const float* src = srcs[a];
            int n = s.rows * s.pad;
            for (int t = tid; t < n; t += 128) {
                int r = t / s.pad, c = t - r * s.pad;
                float w = (c < s.cols) ? src[r * s.cols + c] : 0.0f;
                smw[s.off + t] = pk(w, w);
            }
        }
        if (tid == 0) { scons[0] = imv[0]; scons[1] = imv[1]; scons[2] = lmbd[0]; }
    }
    __syncthreads();

    long long pair = (long long)blockIdx.x * 128 + tid;
    int i0 = (int)(2 * pair);
    if (i0 >= N) return;
    int i1 = (i0 + 1 < N) ? (i0 + 1) : i0;

    float2 pa = *(const float2*)(x + 2 * (size_t)i0);
    float2 pb = *(const float2*)(x + 2 * (size_t)i1);
    u64 X0 = pk(pa.x, pb.x);
    u64 X1 = pk(pa.y, pb.y);

    // ---- w-MLP: 2 -> 30 -> 30 -> 30 -> 8 (tanh on hidden) ----
    u64 A[30], B[30];
    {
        u64 xin[2] = {X0, X1};
        dense2<2, 30>(smw + OW1, smw + OB1, xin, A);
    }
    tanh_all<30>(A);
    dense2<30, 30>(smw + OW2, smw + OB2, A, B); tanh_all<30>(B);
    dense2<30, 30>(smw + OW3, smw + OB3, B, A); tanh_all<30>(A);
    u64 Wo[8];
    dense2<30, 8>(smw + OW4, smw + OB4, A, Wo);

    // ---- geometry about imv ----
    const float im0 = scons[0], im1 = scons[1], lm = scons[2];
    float xa0, xB0, xa1, xB1;
    upk(X0, xa0, xB0); upk(X1, xa1, xB1);

    float dA0 = xa0 - im0, dA1 = xa1 - im1;
    float rsA = fmaf(dA0, dA0, dA1 * dA1);
    float riA = rsqrtf(rsA);
    float rA  = rsA * riA;
    float cbA = dA0 * riA, sbA = dA1 * riA;

    float dB0 = xB0 - im0, dB1 = xB1 - im1;
    float rsB = fmaf(dB0, dB0, dB1 * dB1);
    float riB = rsqrtf(rsB);
    float rB  = rsB * riB;
    float cbB = dB0 * riB, sbB = dB1 * riB;

    // ---- phi-MLP: 2 -> 15 -> 15 -> 15 -> 4 on unit vectors (padded to 16) ----
    u64 P_[16], Q_[16];
    {
        u64 xin[2] = {pk(cbA, cbB), pk(sbA, sbB)};
        dense2<2, 16>(smw + OP1, smw + OPB1, xin, P_);
    }
    tanh_all<15>(P_);
    dense2<15, 16>(smw + OP2, smw + OPB2, P_, Q_); tanh_all<15>(Q_);
    dense2<15, 16>(smw + OP3, smw + OPB3, Q_, P_); tanh_all<15>(P_);
    u64 Ph[4];
    dense2<15, 4>(smw + OP4, smw + OPB4, P_, Ph);

    // ---- unpack heads and finish per point ----
    float wA[8], wB[8], pA[4], pB[4];
#pragma unroll
    for (int j = 0; j < 8; j++) upk(Wo[j], wA[j], wB[j]);
#pragma unroll
    for (int j = 0; j < 4; j++) upk(Ph[j], pA[j], pB[j]);

    float eA = epilogue(xa0, xa1, rA, cbA, sbA, wA, pA, lm);
    out[i0] = eA;
    if (i1 != i0) {
        float eB = epilogue(xB0, xB1, rB, cbB, sbB, wB, pB, lm);
        out[i1] = eB;
    }
}

extern "C" void kernel_launch(void* const* d_in, const int* in_sizes, int n_in,
                              void* d_out, int out_size)
{
    const float* x    = (const float*)d_in[0];
    const float* imv  = (const float*)d_in[1];
    const float* lmbd = (const float*)d_in[2];
    const float* Ww1  = (const float*)d_in[3];
    const float* bw1  = (const float*)d_in[4];
    const float* Ww2  = (const float*)d_in[5];
    const float* bw2  = (const float*)d_in[6];
    const float* Ww3  = (const float*)d_in[7];
    const float* bw3  = (const float*)d_in[8];
    const float* Ww4  = (const float*)d_in[9];
    const float* bw4  = (const float*)d_in[10];
    const float* Wp1  = (const float*)d_in[11];
    const float* bp1  = (const float*)d_in[12];
    const float* Wp2  = (const float*)d_in[13];
    const float* bp2  = (const float*)d_in[14];
    const float* Wp3  = (const float*)d_in[15];
    const float* bp3  = (const float*)d_in[16];
    const float* Wp4  = (const float*)d_in[17];
    const float* bp4  = (const float*)d_in[18];

    int N = out_size;
    long long pairs = ((long long)N + 1) / 2;
    int blocks = (int)((pairs + 127) / 128);

    mlp2d_kernel<<<blocks, 128>>>(x, imv, lmbd,
                                  Ww1, bw1, Ww2, bw2, Ww3, bw3, Ww4, bw4,
                                  Wp1, bp1, Wp2, bp2, Wp3, bp3, Wp4, bp4,
                                  (float*)d_out, N);
}

// round 3
// speedup vs baseline: 1.2291x; 1.2291x over previous
#include <cuda_runtime.h>

typedef unsigned long long u64;

// ---------------- packed f32x2 primitives (sm_103a) ----------------
static __device__ __forceinline__ u64 pk(float lo, float hi) {
    u64 r; asm("mov.b64 %0, {%1, %2};" : "=l"(r) : "f"(lo), "f"(hi)); return r;
}
static __device__ __forceinline__ void upk(u64 v, float& lo, float& hi) {
    asm("mov.b64 {%0, %1}, %2;" : "=f"(lo), "=f"(hi) : "l"(v));
}
static __device__ __forceinline__ u64 ffma2(u64 a, u64 b, u64 c) {
    u64 d; asm("fma.rn.f32x2 %0, %1, %2, %3;" : "=l"(d) : "l"(a), "l"(b), "l"(c)); return d;
}

// single-MUFU tanh (MUFU.TANH, sm_75+); max err ~2^-10.7 per activation
static __device__ __forceinline__ float tanh_hw(float x) {
    float y; asm("tanh.approx.f32 %0, %1;" : "=f"(y) : "f"(x)); return y;
}
static __device__ __forceinline__ u64 tanh2(u64 v) {
    float a, b; upk(v, a, b);
    return pk(tanh_hw(a), tanh_hw(b));
}

// ---------------- shared-memory weight layout (u64 = {w,w} dup pairs) ----------------
// All segment offsets EVEN (16B-aligned), row strides even -> LDS.128 weight fetch.
static constexpr int OW1  = 0;              // [2][30]
static constexpr int OB1  = OW1  + 60;      // [30]
static constexpr int OW2  = OB1  + 30;      // [30][30]
static constexpr int OB2  = OW2  + 900;     // [30]
static constexpr int OW3  = OB2  + 30;      // [30][30]
static constexpr int OB3  = OW3  + 900;     // [30]
static constexpr int OW4  = OB3  + 30;      // [30][8]
static constexpr int OB4  = OW4  + 240;     // [8]
static constexpr int OP1  = OB4  + 8;       // [2][16]  (15 real cols, col 15 = 0)
static constexpr int OPB1 = OP1  + 32;      // [16]
static constexpr int OP2  = OPB1 + 16;      // [15][16]
static constexpr int OPB2 = OP2  + 240;     // [16]
static constexpr int OP3  = OPB2 + 16;      // [15][16]
static constexpr int OPB3 = OP3  + 240;     // [16]
static constexpr int OP4  = OPB3 + 16;      // [15][4]
static constexpr int OPB4 = OP4  + 60;      // [4]
static constexpr int SMW_TOTAL = OPB4 + 4;  // 2822 u64 = 22576 B

// ---------------- dense layer with paired (LDS.128) weight loads ----------------
template <int NI, int NO>
static __device__ __forceinline__ void dense2(const u64* __restrict__ W,
                                              const u64* __restrict__ Bias,
                                              const u64* __restrict__ in,
                                              u64* __restrict__ out) {
#pragma unroll
    for (int j = 0; j < NO; j += 2) {
        ulonglong2 b2 = *(const ulonglong2*)(Bias + j);
        out[j] = b2.x; out[j + 1] = b2.y;
    }
#pragma unroll
    for (int k = 0; k < NI; k++) {
        u64 hk = in[k];
#pragma unroll
        for (int j = 0; j < NO; j += 2) {
            ulonglong2 w2 = *(const ulonglong2*)(W + k * NO + j);
            out[j]     = ffma2(w2.x, hk, out[j]);
            out[j + 1] = ffma2(w2.y, hk, out[j + 1]);
        }
    }
}
template <int NN>
static __device__ __forceinline__ void tanh_all(u64* v) {
#pragma unroll
    for (int j = 0; j < NN; j++) v[j] = tanh2(v[j]);
}

// ---------------- half-angle: sin(θ/2), cos(θ/2) from cosθ, sinθ ----------------
static __device__ __forceinline__ void halfang(float c, float sn, float& sh, float& ch) {
    ch = sqrtf(fmaxf(0.0f, 0.5f * (1.0f + c)));
    float sh_a = copysignf(sqrtf(fmaxf(0.0f, 0.5f * (1.0f - c))), sn);
    float sh_b = __fdividef(0.5f * sn, ch);
    sh = (ch > 0.1f) ? sh_b : sh_a;
}

// ---------------- per-point epilogue ----------------
static __device__ __forceinline__ float epilogue(
    float x0, float x1, float r, float cb, float sb,
    const float* wv, const float* pv, float lm)
{
    float s2  = fmaf(x0, x0, x1 * x1);
    float ri0 = rsqrtf(s2);
    float r0  = s2 * ri0;
    float c   = x0 * ri0, sn = x1 * ri0;
    float sh, ch; halfang(c, sn, sh, ch);
    float sq  = sqrtf(r0);
    float v0  = sq * sh;
    float v1  = r0 * sn;
    float v2  = (r0 * sq) * fmaf(sn, ch, c * sh);
    float shb, chb; halfang(cb, sb, shb, chb);
    float u0 = shb, u1 = sb, u2 = fmaf(sb, chb, cb * shb);
    float t  = fminf(fmaxf(fmaf(2.5f, r, -1.25f), 0.0f), 1.0f);
    float t3 = t * t * t;
    float yita = fmaf(fmaf(fmaf(-6.0f, t, 15.0f), t, -10.0f), t3, 1.0f);
    float rp = wv[0] + yita * wv[4]
             + fmaf(wv[5], yita, wv[1]) * v0
             + fmaf(wv[6], yita, wv[2]) * v1
             + fmaf(wv[7], yita, wv[3]) * v2;
    float s  = fmaf(pv[1], u0, fmaf(pv[2], u1, fmaf(pv[3], u2, pv[0])));
    float sp = s * yita * __powf(r, lm);
    return rp + sp;
}

// ---------------- kernel: 2 points per thread, packed into f32x2 lanes ----------------
__global__ void __launch_bounds__(128)
mlp2d_kernel(const float* __restrict__ x,   const float* __restrict__ imv,
             const float* __restrict__ lmbd,
             const float* __restrict__ Ww1, const float* __restrict__ bw1,
             const float* __restrict__ Ww2, const float* __restrict__ bw2,
             const float* __restrict__ Ww3, const float* __restrict__ bw3,
             const float* __restrict__ Ww4, const float* __restrict__ bw4,
             const float* __restrict__ Wp1, const float* __restrict__ bp1,
             const float* __restrict__ Wp2, const float* __restrict__ bp2,
             const float* __restrict__ Wp3, const float* __restrict__ bp3,
             const float* __restrict__ Wp4, const float* __restrict__ bp4,
             float* __restrict__ out, int N)
{
    __shared__ alignas(16) u64 smw[SMW_TOTAL];
    __shared__ float scons[3];

    const int tid = threadIdx.x;
    // cooperative duplicated-pair weight load with column padding (zeros)
    {
        struct Seg { int off; int rows; int cols; int pad; };
        const Seg segs[16] = {
            {OW1, 2, 30, 30}, {OB1, 1, 30, 30},
            {OW2, 30, 30, 30}, {OB2, 1, 30, 30},
            {OW3, 30, 30, 30}, {OB3, 1, 30, 30},
            {OW4, 30, 8, 8},   {OB4, 1, 8, 8},
            {OP1, 2, 15, 16},  {OPB1, 1, 15, 16},
            {OP2, 15, 15, 16}, {OPB2, 1, 15, 16},
            {OP3, 15, 15, 16}, {OPB3, 1, 15, 16},
            {OP4, 15, 4, 4},   {OPB4, 1, 4, 4},
        };
        const float* srcs[16] = {Ww1, bw1, Ww2, bw2, Ww3, bw3, Ww4, bw4,
                                 Wp1, bp1, Wp2, bp2, Wp3, bp3, Wp4, bp4};
        for (int a = 0; a < 16; a++) {
            const Seg s = segs[a];
            const float* src = srcs[a];
            int n = s.rows * s.pad;
            for (int t = tid; t < n; t += 128) {
                int r = t / s.pad, c = t - r * s.pad;
                float w = (c < s.cols) ? src[r * s.cols + c] : 0.0f;
                smw[s.off + t] = pk(w, w);
            }
        }
        if (tid == 0) { scons[0] = imv[0]; scons[1] = imv[1]; scons[2] = lmbd[0]; }
    }
    __syncthreads();

    long long pair = (long long)blockIdx.x * 128 + tid;
    int i0 = (int)(2 * pair);
    if (i0 >= N) return;
    const bool full = (i0 + 1 < N);
    int i1 = full ? (i0 + 1) : i0;

    float xa0, xa1, xB0, xB1;
    if (full) {
        float4 p = *(const float4*)(x + 2 * (size_t)i0);   // {xa0,xa1,xb0,xb1}
        xa0 = p.x; xa1 = p.y; xB0 = p.z; xB1 = p.w;
    } else {
        float2 p = *(const float2*)(x + 2 * (size_t)i0);
        xa0 = xB0 = p.x; xa1 = xB1 = p.y;
    }
    u64 X0 = pk(xa0, xB0);
    u64 X1 = pk(xa1, xB1);

    // ---- w-MLP: 2 -> 30 -> 30 -> 30 -> 8 (tanh on hidden) ----
    u64 A[30], B[30];
    {
        u64 xin[2] = {X0, X1};
        dense2<2, 30>(smw + OW1, smw + OB1, xin, A);
    }
    tanh_all<30>(A);
    dense2<30, 30>(smw + OW2, smw + OB2, A, B); tanh_all<30>(B);
    dense2<30, 30>(smw + OW3, smw + OB3, B, A); tanh_all<30>(A);
    u64 Wo[8];
    dense2<30, 8>(smw + OW4, smw + OB4, A, Wo);

    // ---- geometry about imv ----
    const float im0 = scons[0], im1 = scons[1], lm = scons[2];

    float dA0 = xa0 - im0, dA1 = xa1 - im1;
    float rsA = fmaf(dA0, dA0, dA1 * dA1);
    float riA = rsqrtf(rsA);
    float rA  = rsA * riA;
    float cbA = dA0 * riA, sbA = dA1 * riA;

    float dB0 = xB0 - im0, dB1 = xB1 - im1;
    float rsB = fmaf(dB0, dB0, dB1 * dB1);
    float riB = rsqrtf(rsB);
    float rB  = rsB * riB;
    float cbB = dB0 * riB, sbB = dB1 * riB;

    // ---- phi-MLP: 2 -> 15 -> 15 -> 15 -> 4 on unit vectors (padded to 16) ----
    u64 P_[16], Q_[16];
    {
        u64 xin[2] = {pk(cbA, cbB), pk(sbA, sbB)};
        dense2<2, 16>(smw + OP1, smw + OPB1, xin, P_);
    }
    tanh_all<15>(P_);
    dense2<15, 16>(smw + OP2, smw + OPB2, P_, Q_); tanh_all<15>(Q_);
    dense2<15, 16>(smw + OP3, smw + OPB3, Q_, P_); tanh_all<15>(P_);
    u64 Ph[4];
    dense2<15, 4>(smw + OP4, smw + OPB4, P_, Ph);

    // ---- unpack heads and finish per point ----
    float wA[8], wB[8], pA[4], pB[4];
#pragma unroll
    for (int j = 0; j < 8; j++) upk(Wo[j], wA[j], wB[j]);
#pragma unroll
    for (int j = 0; j < 4; j++) upk(Ph[j], pA[j], pB[j]);

    float eA = epilogue(xa0, xa1, rA, cbA, sbA, wA, pA, lm);
    if (full) {
        float eB = epilogue(xB0, xB1, rB, cbB, sbB, wB, pB, lm);
        *(float2*)(out + i0) = make_float2(eA, eB);
    } else {
        out[i0] = eA;
    }
}

extern "C" void kernel_launch(void* const* d_in, const int* in_sizes, int n_in,
                              void* d_out, int out_size)
{
    const float* x    = (const float*)d_in[0];
    const float* imv  = (const float*)d_in[1];
    const float* lmbd = (const float*)d_in[2];
    const float* Ww1  = (const float*)d_in[3];
    const float* bw1  = (const float*)d_in[4];
    const float* Ww2  = (const float*)d_in[5];
    const float* bw2  = (const float*)d_in[6];
    const float* Ww3  = (const float*)d_in[7];
    const float* bw3  = (const float*)d_in[8];
    const float* Ww4  = (const float*)d_in[9];
    const float* bw4  = (const float*)d_in[10];
    const float* Wp1  = (const float*)d_in[11];
    const float* bp1  = (const float*)d_in[12];
    const float* Wp2  = (const float*)d_in[13];
    const float* bp2  = (const float*)d_in[14];
    const float* Wp3  = (const float*)d_in[15];
    const float* bp3  = (const float*)d_in[16];
    const float* Wp4  = (const float*)d_in[17];
    const float* bp4  = (const float*)d_in[18];

    int N = out_size;
    long long pairs = ((long long)N + 1) / 2;
    int blocks = (int)((pairs + 127) / 128);

    mlp2d_kernel<<<blocks, 128>>>(x, imv, lmbd,
                                  Ww1, bw1, Ww2, bw2, Ww3, bw3, Ww4, bw4,
                                  Wp1, bp1, Wp2, bp2, Wp3, bp3, Wp4, bp4,
                                  (float*)d_out, N);
}

// round 4
// speedup vs baseline: 1.6167x; 1.3153x over previous
#include <cuda_runtime.h>

typedef unsigned long long u64;

// ---------------- packed f32x2 primitives (sm_103a) ----------------
static __device__ __forceinline__ u64 pk(float lo, float hi) {
    u64 r; asm("mov.b64 %0, {%1, %2};" : "=l"(r) : "f"(lo), "f"(hi)); return r;
}
static __device__ __forceinline__ void upk(u64 v, float& lo, float& hi) {
    asm("mov.b64 {%0, %1}, %2;" : "=f"(lo), "=f"(hi) : "l"(v));
}
static __device__ __forceinline__ u64 ffma2(u64 a, u64 b, u64 c) {
    u64 d; asm("fma.rn.f32x2 %0, %1, %2, %3;" : "=l"(d) : "l"(a), "l"(b), "l"(c)); return d;
}

// single-MUFU tanh (MUFU.TANH)
static __device__ __forceinline__ float tanh_hw(float x) {
    float y; asm("tanh.approx.f32 %0, %1;" : "=f"(y) : "f"(x)); return y;
}
static __device__ __forceinline__ u64 tanh2(u64 v) {
    float a, b; upk(v, a, b);
    return pk(tanh_hw(a), tanh_hw(b));
}

// ---------------- shared-memory weight layout (plain floats, padded cols) ----------------
static constexpr int OW1  = 0;      // [2][32]
static constexpr int OB1  = 64;     // [32]
static constexpr int OW2  = 96;     // [30][32]
static constexpr int OB2  = 1056;   // [32]
static constexpr int OW3  = 1088;   // [30][32]
static constexpr int OB3  = 2048;   // [32]
static constexpr int OW4  = 2080;   // [30][8]
static constexpr int OB4  = 2320;   // [8]
static constexpr int OP1  = 2328;   // [2][16]
static constexpr int OPB1 = 2360;   // [16]
static constexpr int OP2  = 2376;   // [15][16]
static constexpr int OPB2 = 2616;   // [16]
static constexpr int OP3  = 2632;   // [15][16]
static constexpr int OPB3 = 2872;   // [16]
static constexpr int OP4  = 2888;   // [15][4]
static constexpr int OPB4 = 2948;   // [4]
static constexpr int SMW_TOTAL = 2952;  // floats = 11808 B

// ---------------- dense layer, neuron-pair lanes, 2 points per thread ----------------
// W is [NI][NOP] padded row-major in smem, NOP % 4 == 0, rows 16B-aligned.
// Activations are held as packed pairs of CONSECUTIVE NEURONS per point:
// hA[p] = {h_2p, h_2p+1} for point A. Output accumulators same layout.
template <int NI, int NOP>
static __device__ __forceinline__ void dense_pp(const float* __restrict__ Wm,
                                                const float* __restrict__ Bs,
                                                const u64* __restrict__ hA,
                                                const u64* __restrict__ hB,
                                                u64* __restrict__ accA,
                                                u64* __restrict__ accB)
{
#pragma unroll
    for (int jp = 0; jp < NOP / 2; jp++) {
        float2 b = *(const float2*)(Bs + 2 * jp);
        u64 bp = pk(b.x, b.y);
        accA[jp] = bp; accB[jp] = bp;
    }
#pragma unroll
    for (int k = 0; k < NI; k++) {
        float alo, ahi; upk(hA[k >> 1], alo, ahi);
        float blo, bhi; upk(hB[k >> 1], blo, bhi);
        float av = (k & 1) ? ahi : alo;
        float bv = (k & 1) ? bhi : blo;
        u64 dA = pk(av, av);
        u64 dB = pk(bv, bv);
#pragma unroll
        for (int jq = 0; jq < NOP / 4; jq++) {
            float4 w = *(const float4*)(Wm + k * NOP + 4 * jq);
            u64 w01 = pk(w.x, w.y), w23 = pk(w.z, w.w);
            accA[2 * jq]     = ffma2(w01, dA, accA[2 * jq]);
            accA[2 * jq + 1] = ffma2(w23, dA, accA[2 * jq + 1]);
            accB[2 * jq]     = ffma2(w01, dB, accB[2 * jq]);
            accB[2 * jq + 1] = ffma2(w23, dB, accB[2 * jq + 1]);
        }
    }
}
template <int NP>
static __device__ __forceinline__ void tanh_pairs(u64* a, u64* b) {
#pragma unroll
    for (int j = 0; j < NP; j++) { a[j] = tanh2(a[j]); b[j] = tanh2(b[j]); }
}

// ---------------- half-angle: sin(θ/2), cos(θ/2) from cosθ, sinθ ----------------
static __device__ __forceinline__ void halfang(float c, float sn, float& sh, float& ch) {
    ch = sqrtf(fmaxf(0.0f, 0.5f * (1.0f + c)));
    float sh_a = copysignf(sqrtf(fmaxf(0.0f, 0.5f * (1.0f - c))), sn);
    float sh_b = __fdividef(0.5f * sn, ch);
    sh = (ch > 0.1f) ? sh_b : sh_a;
}

// ---------------- per-point epilogue ----------------
static __device__ __forceinline__ float epilogue(
    float x0, float x1, float r, float cb, float sb,
    const float* wv, const float* pv, float lm)
{
    float s2  = fmaf(x0, x0, x1 * x1);
    float ri0 = rsqrtf(s2);
    float r0  = s2 * ri0;
    float c   = x0 * ri0, sn = x1 * ri0;
    float sh, ch; halfang(c, sn, sh, ch);
    float sq  = sqrtf(r0);
    float v0  = sq * sh;
    float v1  = r0 * sn;
    float v2  = (r0 * sq) * fmaf(sn, ch, c * sh);
    float shb, chb; halfang(cb, sb, shb, chb);
    float u0 = shb, u1 = sb, u2 = fmaf(sb, chb, cb * shb);
    float t  = fminf(fmaxf(fmaf(2.5f, r, -1.25f), 0.0f), 1.0f);
    float t3 = t * t * t;
    float yita = fmaf(fmaf(fmaf(-6.0f, t, 15.0f), t, -10.0f), t3, 1.0f);
    float rp = wv[0] + yita * wv[4]
             + fmaf(wv[5], yita, wv[1]) * v0
             + fmaf(wv[6], yita, wv[2]) * v1
             + fmaf(wv[7], yita, wv[3]) * v2;
    float s  = fmaf(pv[1], u0, fmaf(pv[2], u1, fmaf(pv[3], u2, pv[0])));
    float sp = s * yita * __powf(r, lm);
    return rp + sp;
}

// ---------------- kernel: 2 points per thread ----------------
__global__ void __launch_bounds__(128)
mlp2d_kernel(const float* __restrict__ x,   const float* __restrict__ imv,
             const float* __restrict__ lmbd,
             const float* __restrict__ Ww1, const float* __restrict__ bw1,
             const float* __restrict__ Ww2, const float* __restrict__ bw2,
             const float* __restrict__ Ww3, const float* __restrict__ bw3,
             const float* __restrict__ Ww4, const float* __restrict__ bw4,
             const float* __restrict__ Wp1, const float* __restrict__ bp1,
             const float* __restrict__ Wp2, const float* __restrict__ bp2,
             const float* __restrict__ Wp3, const float* __restrict__ bp3,
             const float* __restrict__ Wp4, const float* __restrict__ bp4,
             float* __restrict__ out, int N)
{
    __shared__ alignas(16) float smw[SMW_TOTAL];
    __shared__ float scons[3];

    const int tid = threadIdx.x;
    // cooperative plain weight load with zero column padding
    {
        struct Seg { int off; int rows; int cols; int pad; };
        const Seg segs[16] = {
            {OW1, 2, 30, 32},  {OB1, 1, 30, 32},
            {OW2, 30, 30, 32}, {OB2, 1, 30, 32},
            {OW3, 30, 30, 32}, {OB3, 1, 30, 32},
            {OW4, 30, 8, 8},   {OB4, 1, 8, 8},
            {OP1, 2, 15, 16},  {OPB1, 1, 15, 16},
            {OP2, 15, 15, 16}, {OPB2, 1, 15, 16},
            {OP3, 15, 15, 16}, {OPB3, 1, 15, 16},
            {OP4, 15, 4, 4},   {OPB4, 1, 4, 4},
        };
        const float* srcs[16] = {Ww1, bw1, Ww2, bw2, Ww3, bw3, Ww4, bw4,
                                 Wp1, bp1, Wp2, bp2, Wp3, bp3, Wp4, bp4};
        for (int a = 0; a < 16; a++) {
            const Seg s = segs[a];
            const float* src = srcs[a];
            int n = s.rows * s.pad;
            for (int t = tid; t < n; t += 128) {
                int r = t / s.pad, c = t - r * s.pad;
                smw[s.off + t] = (c < s.cols) ? src[r * s.cols + c] : 0.0f;
            }
        }
        if (tid == 0) { scons[0] = imv[0]; scons[1] = imv[1]; scons[2] = lmbd[0]; }
    }
    __syncthreads();

    long long pair = (long long)blockIdx.x * 128 + tid;
    int i0 = (int)(2 * pair);
    if (i0 >= N) return;
    const bool full = (i0 + 1 < N);

    float xa0, xa1, xB0, xB1;
    if (full) {
        float4 p = *(const float4*)(x + 2 * (size_t)i0);
        xa0 = p.x; xa1 = p.y; xB0 = p.z; xB1 = p.w;
    } else {
        float2 p = *(const float2*)(x + 2 * (size_t)i0);
        xa0 = xB0 = p.x; xa1 = xB1 = p.y;
    }

    // ---- w-MLP: 2 -> 30 -> 30 -> 30 -> 8 ----
    u64 A1[16], B1a[16], A2[16], B2a[16];
    {
        u64 hA[1] = {pk(xa0, xa1)};
        u64 hB[1] = {pk(xB0, xB1)};
        dense_pp<2, 32>(smw + OW1, smw + OB1, hA, hB, A1, B1a);
    }
    tanh_pairs<15>(A1, B1a);          // pads (lanes 30,31) unused by NI=30 below
    dense_pp<30, 32>(smw + OW2, smw + OB2, A1, B1a, A2, B2a);
    tanh_pairs<15>(A2, B2a);
    dense_pp<30, 32>(smw + OW3, smw + OB3, A2, B2a, A1, B1a);
    tanh_pairs<15>(A1, B1a);
    u64 WoA[4], WoB[4];
    dense_pp<30, 8>(smw + OW4, smw + OB4, A1, B1a, WoA, WoB);

    // ---- geometry about imv ----
    const float im0 = scons[0], im1 = scons[1], lm = scons[2];

    float dA0 = xa0 - im0, dA1 = xa1 - im1;
    float rsA = fmaf(dA0, dA0, dA1 * dA1);
    float riA = rsqrtf(rsA);
    float rA  = rsA * riA;
    float cbA = dA0 * riA, sbA = dA1 * riA;

    float dB0 = xB0 - im0, dB1 = xB1 - im1;
    float rsB = fmaf(dB0, dB0, dB1 * dB1);
    float riB = rsqrtf(rsB);
    float rB  = rsB * riB;
    float cbB = dB0 * riB, sbB = dB1 * riB;

    // ---- phi-MLP: 2 -> 15 -> 15 -> 15 -> 4 (padded to 16) ----
    u64 PA[8], PB[8], QA[8], QB[8];
    {
        u64 hA[1] = {pk(cbA, sbA)};
        u64 hB[1] = {pk(cbB, sbB)};
        dense_pp<2, 16>(smw + OP1, smw + OPB1, hA, hB, PA, PB);
    }
    tanh_pairs<8>(PA, PB);            // lane 15 is pad (w,b = 0) -> tanh(0)=0, ignored
    dense_pp<15, 16>(smw + OP2, smw + OPB2, PA, PB, QA, QB);
    tanh_pairs<8>(QA, QB);
    dense_pp<15, 16>(smw + OP3, smw + OPB3, QA, QB, PA, PB);
    tanh_pairs<8>(PA, PB);
    u64 PhA[2], PhB[2];
    dense_pp<15, 4>(smw + OP4, smw + OPB4, PA, PB, PhA, PhB);

    // ---- unpack heads and finish per point ----
    float wA[8], wB[8], pA[4], pB[4];
#pragma unroll
    for (int j = 0; j < 4; j++) { upk(WoA[j], wA[2 * j], wA[2 * j + 1]);
                                  upk(WoB[j], wB[2 * j], wB[2 * j + 1]); }
#pragma unroll
    for (int j = 0; j < 2; j++) { upk(PhA[j], pA[2 * j], pA[2 * j + 1]);
                                  upk(PhB[j], pB[2 * j], pB[2 * j + 1]); }

    float eA = epilogue(xa0, xa1, rA, cbA, sbA, wA, pA, lm);
    if (full) {
        float eB = epilogue(xB0, xB1, rB, cbB, sbB, wB, pB, lm);
        *(float2*)(out + i0) = make_float2(eA, eB);
    } else {
        out[i0] = eA;
    }
}

extern "C" void kernel_launch(void* const* d_in, const int* in_sizes, int n_in,
                              void* d_out, int out_size)
{
    const float* x    = (const float*)d_in[0];
    const float* imv  = (const float*)d_in[1];
    const float* lmbd = (const float*)d_in[2];
    const float* Ww1  = (const float*)d_in[3];
    const float* bw1  = (const float*)d_in[4];
    const float* Ww2  = (const float*)d_in[5];
    const float* bw2  = (const float*)d_in[6];
    const float* Ww3  = (const float*)d_in[7];
    const float* bw3  = (const float*)d_in[8];
    const float* Ww4  = (const float*)d_in[9];
    const float* bw4  = (const float*)d_in[10];
    const float* Wp1  = (const float*)d_in[11];
    const float* bp1  = (const float*)d_in[12];
    const float* Wp2  = (const float*)d_in[13];
    const float* bp2  = (const float*)d_in[14];
    const float* Wp3  = (const float*)d_in[15];
    const float* bp3  = (const float*)d_in[16];
    const float* Wp4  = (const float*)d_in[17];
    const float* bp4  = (const float*)d_in[18];

    int N = out_size;
    long long pairs = ((long long)N + 1) / 2;
    int blocks = (int)((pairs + 127) / 128);

    mlp2d_kernel<<<blocks, 128>>>(x, imv, lmbd,
                                  Ww1, bw1, Ww2, bw2, Ww3, bw3, Ww4, bw4,
                                  Wp1, bp1, Wp2, bp2, Wp3, bp3, Wp4, bp4,
                                  (float*)d_out, N);
}